// round 1
// baseline (speedup 1.0000x reference)
#include <cuda_runtime.h>
#include <cuda_bf16.h>
#include <math.h>

// Problem dims
#define B_   32
#define S_   60
#define T_   40
#define H_   512    // ZH_HIDDEN
#define E_   512    // RNN_ENC
#define A_   256    // ATT
#define D_   256    // ZH_DIMS
#define C_   256    // CNN_ENC
#define V_   50000  // ZH_VOC
#define IN_SZ 1024  // E_ + C_ + D_
#define G4   2048   // 4*H_

// Scratch (device globals — no allocation allowed)
__device__ float d_Uh[B_ * S_ * A_];
__device__ float d_WsT[H_ * A_];      // W_ws^T  [k][a]
__device__ float d_WuT[E_ * A_];      // W_uh^T  [k][a]
__device__ float d_inpT[IN_SZ * B_];  // k-major LSTM input
__device__ float d_hxT[H_ * B_];      // k-major hidden
__device__ float d_cx[B_ * H_];
__device__ float d_gatesT[G4 * B_];
__device__ float d_Hall[T_ * B_ * H_]; // [t][b][j]

__device__ __forceinline__ float sigf(float x) { return 1.0f / (1.0f + expf(-x)); }

// ---------------------------------------------------------------------------
// One-time setup: transpose W_ws / W_uh, install cnn_enc slice of inpT
// ---------------------------------------------------------------------------
__global__ void setup_kernel(const float* __restrict__ W_ws,
                             const float* __restrict__ W_uh,
                             const float* __restrict__ cnn) {
    int i = blockIdx.x * blockDim.x + threadIdx.x;
    if (i < A_ * H_) { int a = i / H_; int k = i % H_; d_WsT[k * A_ + a] = W_ws[i]; }
    if (i < A_ * E_) { int a = i / E_; int k = i % E_; d_WuT[k * A_ + a] = W_uh[i]; }
    if (i < B_ * C_) { int b = i / C_; int c = i % C_; d_inpT[(E_ + c) * B_ + b] = cnn[i]; }
}

// ---------------------------------------------------------------------------
// Uh[b,s,:] = rnn_enc[b,s,:] @ W_uh^T + b_uh     (grid = B_*S_, 256 thr)
// ---------------------------------------------------------------------------
__global__ void uh_kernel(const float* __restrict__ rnn,
                          const float* __restrict__ b_uh) {
    __shared__ float sr[E_];
    int bs = blockIdx.x;
    const float* row = rnn + (long)bs * E_;
    for (int k = threadIdx.x; k < E_; k += 256) sr[k] = row[k];
    __syncthreads();
    int a = threadIdx.x;
    float acc = b_uh[a];
#pragma unroll 8
    for (int k = 0; k < E_; k++) acc += sr[k] * d_WuT[k * A_ + a];
    d_Uh[bs * A_ + a] = acc;
}

// ---------------------------------------------------------------------------
// Per-step fused kernel (grid = B_, 512 thr):
//   1) LSTM pointwise for step t-1 (gates -> hx,cx,Hall[t-1])   [skipped t=0]
//   2) ws = hx @ W_ws^T + b_ws
//   3) score -> softmax -> alpha
//   4) atten -> inpT[0:512];  g_t embedding -> inpT[768:1024]
// ---------------------------------------------------------------------------
__global__ void attn_kernel(int t,
                            const float* __restrict__ rnn,
                            const float* __restrict__ emb,
                            const int*   __restrict__ gtruths,
                            const float* __restrict__ W_v,
                            const float* __restrict__ b_v,
                            const float* __restrict__ b_ws) {
    int b = blockIdx.x;
    int tid = threadIdx.x;
    __shared__ float s_h[H_];
    __shared__ float s_ws[A_];
    __shared__ float s_score[S_];
    __shared__ float s_alpha[S_];

    if (t == 0) {
        s_h[tid] = 0.0f;
        d_hxT[tid * B_ + b] = 0.0f;
        d_cx[b * H_ + tid] = 0.0f;
    } else {
        int j = tid;
        float gi = d_gatesT[j * B_ + b];
        float gf = d_gatesT[(H_ + j) * B_ + b];
        float gg = d_gatesT[(2 * H_ + j) * B_ + b];
        float go = d_gatesT[(3 * H_ + j) * B_ + b];
        float c = sigf(gf) * d_cx[b * H_ + j] + sigf(gi) * tanhf(gg);
        float h = sigf(go) * tanhf(c);
        d_cx[b * H_ + j] = c;
        s_h[j] = h;
        d_hxT[j * B_ + b] = h;
        d_Hall[((long)(t - 1) * B_ + b) * H_ + j] = h;
    }
    __syncthreads();

    // ws
    if (tid < A_) {
        float acc = b_ws[tid];
#pragma unroll 8
        for (int k = 0; k < H_; k++) acc += s_h[k] * d_WsT[k * A_ + tid];
        s_ws[tid] = acc;
    }
    __syncthreads();

    // scores: 16 warps; warp w handles s = w, w+16, ...
    int w = tid >> 5, lane = tid & 31;
    float bv0 = b_v[0];
    for (int s = w; s < S_; s += 16) {
        const float* uh = d_Uh + ((long)b * S_ + s) * A_;
        float p = 0.0f;
#pragma unroll
        for (int a = lane; a < A_; a += 32)
            p += tanhf(uh[a] + s_ws[a]) * W_v[a];
#pragma unroll
        for (int off = 16; off; off >>= 1) p += __shfl_down_sync(0xffffffffu, p, off);
        if (lane == 0) s_score[s] = p + bv0;
    }
    __syncthreads();

    // softmax by warp 0
    if (w == 0) {
        float m = -1e30f;
        for (int s = lane; s < S_; s += 32) m = fmaxf(m, s_score[s]);
#pragma unroll
        for (int off = 16; off; off >>= 1) m = fmaxf(m, __shfl_xor_sync(0xffffffffu, m, off));
        float sum = 0.0f;
        for (int s = lane; s < S_; s += 32) { float e = expf(s_score[s] - m); s_alpha[s] = e; sum += e; }
#pragma unroll
        for (int off = 16; off; off >>= 1) sum += __shfl_xor_sync(0xffffffffu, sum, off);
        float inv = 1.0f / sum;
        for (int s = lane; s < S_; s += 32) s_alpha[s] *= inv;
    }
    __syncthreads();

    // atten: e = tid (512 dims)
    {
        const float* r = rnn + (long)b * S_ * E_ + tid;
        float acc = 0.0f;
#pragma unroll 4
        for (int s = 0; s < S_; s++) acc += s_alpha[s] * r[(long)s * E_];
        d_inpT[tid * B_ + b] = acc;
    }
    // g_t embedding
    if (tid < D_) {
        int tok = gtruths[b * T_ + t];
        d_inpT[(E_ + C_ + tid) * B_ + b] = emb[(long)tok * D_ + tid];
    }
}

// ---------------------------------------------------------------------------
// gates[g, b] = W_ih[g,:]·inp[b,:] + W_hh[g,:]·hx[b,:] + b_ih[g] + b_hh[g]
// grid = G4/8 blocks, 256 thr; warp per gate row, lane = batch
// ---------------------------------------------------------------------------
__global__ void lstm_kernel(const float* __restrict__ W_ih,
                            const float* __restrict__ b_ih,
                            const float* __restrict__ W_hh,
                            const float* __restrict__ b_hh) {
    int g = blockIdx.x * 8 + (threadIdx.x >> 5);
    int lane = threadIdx.x & 31;
    float acc = b_ih[g] + b_hh[g];
    const float4* wi = (const float4*)(W_ih + (long)g * IN_SZ);
#pragma unroll 4
    for (int k4 = 0; k4 < IN_SZ / 4; k4++) {
        float4 wv = wi[k4];
        int k = k4 * 4;
        acc += wv.x * d_inpT[(k + 0) * B_ + lane];
        acc += wv.y * d_inpT[(k + 1) * B_ + lane];
        acc += wv.z * d_inpT[(k + 2) * B_ + lane];
        acc += wv.w * d_inpT[(k + 3) * B_ + lane];
    }
    const float4* wh = (const float4*)(W_hh + (long)g * H_);
#pragma unroll 4
    for (int k4 = 0; k4 < H_ / 4; k4++) {
        float4 wv = wh[k4];
        int k = k4 * 4;
        acc += wv.x * d_hxT[(k + 0) * B_ + lane];
        acc += wv.y * d_hxT[(k + 1) * B_ + lane];
        acc += wv.z * d_hxT[(k + 2) * B_ + lane];
        acc += wv.w * d_hxT[(k + 3) * B_ + lane];
    }
    d_gatesT[g * B_ + lane] = acc;
}

// Final pointwise: gates of step T_-1 -> Hall[T_-1]   (grid B_, 512 thr)
__global__ void final_pw_kernel() {
    int b = blockIdx.x;
    int j = threadIdx.x;
    float gi = d_gatesT[j * B_ + b];
    float gf = d_gatesT[(H_ + j) * B_ + b];
    float gg = d_gatesT[(2 * H_ + j) * B_ + b];
    float go = d_gatesT[(3 * H_ + j) * B_ + b];
    float c = sigf(gf) * d_cx[b * H_ + j] + sigf(gi) * tanhf(gg);
    float h = sigf(go) * tanhf(c);
    d_Hall[((long)(T_ - 1) * B_ + b) * H_ + j] = h;
}

// ---------------------------------------------------------------------------
// Logits GEMM: out[m, v] = Hall[m,:]·W_fc[v,:] + b_fc[v]
// M=1280 (t*B_+b), N=50000, K=512.  128x128x8 tiles, 8x8 per thread.
// ---------------------------------------------------------------------------
#define GBM 128
#define GBN 128
#define GBK 8
__global__ __launch_bounds__(256, 2)
void gemm_kernel(const float* __restrict__ Wfc,
                 const float* __restrict__ bfc,
                 float* __restrict__ out) {
    __shared__ float As[GBK][GBM];
    __shared__ float Bs[GBK][GBN];
    int m0 = blockIdx.y * GBM;
    int n0 = blockIdx.x * GBN;
    int tid = threadIdx.x;
    int ar = tid >> 1;          // 0..127
    int ac = (tid & 1) * 4;     // 0 or 4
    int tx = tid & 15, ty = tid >> 4;

    float acc[8][8];
#pragma unroll
    for (int i = 0; i < 8; i++)
#pragma unroll
        for (int j = 0; j < 8; j++) acc[i][j] = 0.0f;

    int nrow = n0 + ar;
    const float* Arow = d_Hall + (long)(m0 + ar) * H_ + ac;
    const float* Brow = (nrow < V_) ? (Wfc + (long)nrow * H_ + ac) : nullptr;

    for (int k0 = 0; k0 < H_; k0 += GBK) {
        float4 av = *(const float4*)(Arow + k0);
        As[ac + 0][ar] = av.x; As[ac + 1][ar] = av.y;
        As[ac + 2][ar] = av.z; As[ac + 3][ar] = av.w;
        float4 bv = Brow ? *(const float4*)(Brow + k0) : make_float4(0.f, 0.f, 0.f, 0.f);
        Bs[ac + 0][ar] = bv.x; Bs[ac + 1][ar] = bv.y;
        Bs[ac + 2][ar] = bv.z; Bs[ac + 3][ar] = bv.w;
        __syncthreads();
#pragma unroll
        for (int k = 0; k < GBK; k++) {
            float a[8], b[8];
#pragma unroll
            for (int i = 0; i < 8; i++) a[i] = As[k][ty * 8 + i];
#pragma unroll
            for (int j = 0; j < 8; j++) b[j] = Bs[k][tx * 8 + j];
#pragma unroll
            for (int i = 0; i < 8; i++)
#pragma unroll
                for (int j = 0; j < 8; j++) acc[i][j] += a[i] * b[j];
        }
        __syncthreads();
    }

#pragma unroll
    for (int i = 0; i < 8; i++) {
        int m = m0 + ty * 8 + i;
#pragma unroll
        for (int j = 0; j < 8; j++) {
            int n = n0 + tx * 8 + j;
            if (n < V_) out[(long)m * V_ + n] = acc[i][j] + bfc[n];
        }
    }
}

// ---------------------------------------------------------------------------
// Argmax per logits row; preds.T layout [B_, T_] written as float
// ---------------------------------------------------------------------------
__global__ void argmax_kernel(const float* __restrict__ logits,
                              float* __restrict__ outp) {
    int m = blockIdx.x;  // t*B_+b
    int tid = threadIdx.x;
    __shared__ float sv[256];
    __shared__ int   si[256];
    const float* row = logits + (long)m * V_;
    float best = -INFINITY; int bi = 0;
    for (int v = tid; v < V_; v += 256) {
        float x = row[v];
        if (x > best) { best = x; bi = v; }
    }
    sv[tid] = best; si[tid] = bi;
    __syncthreads();
    for (int s = 128; s; s >>= 1) {
        if (tid < s) {
            if (sv[tid + s] > sv[tid] ||
                (sv[tid + s] == sv[tid] && si[tid + s] < si[tid])) {
                sv[tid] = sv[tid + s]; si[tid] = si[tid + s];
            }
        }
        __syncthreads();
    }
    if (tid == 0) {
        int t = m / B_, b = m % B_;
        outp[b * T_ + t] = (float)si[0];
    }
}

// ---------------------------------------------------------------------------
extern "C" void kernel_launch(void* const* d_in, const int* in_sizes, int n_in,
                              void* d_out, int out_size) {
    const float* rnn   = (const float*)d_in[0];
    const float* cnn   = (const float*)d_in[1];
    const int*   gtr   = (const int*)  d_in[2];
    const float* emb   = (const float*)d_in[3];
    const float* W_ih  = (const float*)d_in[4];
    const float* b_ih  = (const float*)d_in[5];
    const float* W_hh  = (const float*)d_in[6];
    const float* b_hh  = (const float*)d_in[7];
    const float* W_ws  = (const float*)d_in[8];
    const float* b_ws  = (const float*)d_in[9];
    const float* W_uh  = (const float*)d_in[10];
    const float* b_uh  = (const float*)d_in[11];
    const float* W_v   = (const float*)d_in[12];
    const float* b_v   = (const float*)d_in[13];
    const float* W_fc  = (const float*)d_in[14];
    const float* b_fc  = (const float*)d_in[15];
    float* out = (float*)d_out;

    setup_kernel<<<512, 256>>>(W_ws, W_uh, cnn);
    uh_kernel<<<B_ * S_, 256>>>(rnn, b_uh);
    for (int t = 0; t < T_; t++) {
        attn_kernel<<<B_, 512>>>(t, rnn, emb, gtr, W_v, b_v, b_ws);
        lstm_kernel<<<G4 / 8, 256>>>(W_ih, b_ih, W_hh, b_hh);
    }
    final_pw_kernel<<<B_, 512>>>();

    dim3 ggrid((V_ + GBN - 1) / GBN, (T_ * B_) / GBM);
    gemm_kernel<<<ggrid, 256>>>(W_fc, b_fc, out);

    long logits_elems = (long)T_ * B_ * V_;
    if ((long)out_size >= logits_elems + (long)B_ * T_) {
        argmax_kernel<<<T_ * B_, 256>>>(out, out + logits_elems);
    }
}

// round 3
// speedup vs baseline: 1.4129x; 1.4129x over previous
#include <cuda_runtime.h>
#include <cuda_bf16.h>
#include <math.h>

// Problem dims
#define B_   32
#define S_   60
#define T_   40
#define H_   512    // ZH_HIDDEN
#define E_   512    // RNN_ENC
#define A_   256    // ATT
#define D_   256    // ZH_DIMS
#define C_   256    // CNN_ENC
#define V_   50000  // ZH_VOC
#define KTOT 1536   // E_+C_+D_ (=1024) + H_ (=512) concatenated K
#define G4   2048   // 4*H_

// Scratch (device globals — no allocation allowed)
__device__ float d_Uh[B_ * S_ * A_];
__device__ float d_x[B_ * KTOT];       // [b][k]: 0..511 atten | 512..767 cnn | 768..1023 emb | 1024..1535 hx
__device__ float d_cx[B_ * H_];
__device__ float d_gatesT[G4 * B_];    // [gate][b]
__device__ float d_Hall[T_ * B_ * H_]; // [t][b][j]

__device__ __forceinline__ float sigf(float x) { return 1.0f / (1.0f + expf(-x)); }

// ---------------------------------------------------------------------------
// Uh = rnn_enc @ W_uh^T + b_uh  as GEMM  M=1920(b*S+s) N=256 K=512
// 64x64x16 tiles, 256 threads, 4x4 per thread. grid (4, 30)
// ---------------------------------------------------------------------------
__global__ __launch_bounds__(256) void uh_kernel(const float* __restrict__ rnn,
                                                 const float* __restrict__ W_uh,
                                                 const float* __restrict__ b_uh) {
    __shared__ float As[16][68];
    __shared__ float Bs[16][68];
    int m0 = blockIdx.y * 64;
    int n0 = blockIdx.x * 64;
    int tid = threadIdx.x;
    int ar = tid >> 2, ac = (tid & 3) * 4;
    int tx = tid & 15, ty = tid >> 4;
    float acc[4][4];
#pragma unroll
    for (int i = 0; i < 4; i++)
#pragma unroll
        for (int j = 0; j < 4; j++) acc[i][j] = 0.0f;

    for (int k0 = 0; k0 < E_; k0 += 16) {
        float4 a = *(const float4*)(rnn + (long)(m0 + ar) * E_ + k0 + ac);
        float4 b = *(const float4*)(W_uh + (long)(n0 + ar) * E_ + k0 + ac);
        As[ac + 0][ar] = a.x; As[ac + 1][ar] = a.y; As[ac + 2][ar] = a.z; As[ac + 3][ar] = a.w;
        Bs[ac + 0][ar] = b.x; Bs[ac + 1][ar] = b.y; Bs[ac + 2][ar] = b.z; Bs[ac + 3][ar] = b.w;
        __syncthreads();
#pragma unroll
        for (int k = 0; k < 16; k++) {
            float4 av = *(const float4*)&As[k][ty * 4];
            float4 bv = *(const float4*)&Bs[k][tx * 4];
            float aa[4] = {av.x, av.y, av.z, av.w};
            float bb[4] = {bv.x, bv.y, bv.z, bv.w};
#pragma unroll
            for (int i = 0; i < 4; i++)
#pragma unroll
                for (int j = 0; j < 4; j++) acc[i][j] += aa[i] * bb[j];
        }
        __syncthreads();
    }
#pragma unroll
    for (int i = 0; i < 4; i++) {
        int m = m0 + ty * 4 + i;
#pragma unroll
        for (int j = 0; j < 4; j++) {
            int n = n0 + tx * 4 + j;
            d_Uh[(long)m * A_ + n] = acc[i][j] + b_uh[n];
        }
    }
}

// ---------------------------------------------------------------------------
// Per-step fused kernel (grid = B_, 512 thr):
//   1) LSTM pointwise for step t-1 (gates -> hx,cx,Hall[t-1]); t==0: zeros + cnn
//   2) ws = hx @ W_ws^T + b_ws   (k-split x2, float4)
//   3) score -> softmax -> alpha
//   4) atten -> d_x[b][0:512];  g_t embedding -> d_x[b][768:1024]
// ---------------------------------------------------------------------------
__global__ __launch_bounds__(512) void attn_kernel(int t,
                            const float* __restrict__ rnn,
                            const float* __restrict__ cnn,
                            const float* __restrict__ emb,
                            const int*   __restrict__ gtruths,
                            const float* __restrict__ W_ws,
                            const float* __restrict__ b_ws,
                            const float* __restrict__ W_v,
                            const float* __restrict__ b_v) {
    int b = blockIdx.x;
    int tid = threadIdx.x;
    __shared__ __align__(16) float s_h[H_];
    __shared__ float s_ws[A_];
    __shared__ float s_wsp[2][A_];
    __shared__ float s_score[S_];
    __shared__ float s_alpha[S_];

    if (t == 0) {
        s_h[tid] = 0.0f;
        d_x[b * KTOT + 1024 + tid] = 0.0f;
        d_cx[b * H_ + tid] = 0.0f;
        if (tid < C_) d_x[b * KTOT + 512 + tid] = cnn[b * C_ + tid];
    } else {
        int j = tid;
        float gi = d_gatesT[j * B_ + b];
        float gf = d_gatesT[(H_ + j) * B_ + b];
        float gg = d_gatesT[(2 * H_ + j) * B_ + b];
        float go = d_gatesT[(3 * H_ + j) * B_ + b];
        float c = sigf(gf) * d_cx[b * H_ + j] + sigf(gi) * tanhf(gg);
        float h = sigf(go) * tanhf(c);
        d_cx[b * H_ + j] = c;
        s_h[j] = h;
        d_x[b * KTOT + 1024 + j] = h;
        d_Hall[((long)(t - 1) * B_ + b) * H_ + j] = h;
    }
    __syncthreads();

    // ws = s_h @ W_ws^T + b_ws, 2-way k-split
    {
        int a = tid & 255;
        int half = tid >> 8;
        const float* wr = W_ws + (long)a * H_ + half * 256;
        const float* hr = s_h + half * 256;
        float p0 = 0.0f, p1 = 0.0f;
#pragma unroll
        for (int k = 0; k < 256; k += 8) {
            float4 w0 = *(const float4*)(wr + k);
            float4 h0 = *(const float4*)(hr + k);
            float4 w1 = *(const float4*)(wr + k + 4);
            float4 h1 = *(const float4*)(hr + k + 4);
            p0 += w0.x * h0.x + w0.y * h0.y + w0.z * h0.z + w0.w * h0.w;
            p1 += w1.x * h1.x + w1.y * h1.y + w1.z * h1.z + w1.w * h1.w;
        }
        s_wsp[half][a] = p0 + p1;
    }
    __syncthreads();
    if (tid < A_) s_ws[tid] = s_wsp[0][tid] + s_wsp[1][tid] + b_ws[tid];
    __syncthreads();

    // scores: 16 warps; warp w handles s = w, w+16, ...
    int w = tid >> 5, lane = tid & 31;
    float bv0 = b_v[0];
    for (int s = w; s < S_; s += 16) {
        const float* uh = d_Uh + ((long)b * S_ + s) * A_;
        float p = 0.0f;
#pragma unroll
        for (int a = lane; a < A_; a += 32)
            p += tanhf(uh[a] + s_ws[a]) * W_v[a];
#pragma unroll
        for (int off = 16; off; off >>= 1) p += __shfl_down_sync(0xffffffffu, p, off);
        if (lane == 0) s_score[s] = p + bv0;
    }
    __syncthreads();

    // softmax by warp 0
    if (w == 0) {
        float m = -1e30f;
        for (int s = lane; s < S_; s += 32) m = fmaxf(m, s_score[s]);
#pragma unroll
        for (int off = 16; off; off >>= 1) m = fmaxf(m, __shfl_xor_sync(0xffffffffu, m, off));
        float sum = 0.0f;
        for (int s = lane; s < S_; s += 32) { float e = expf(s_score[s] - m); s_alpha[s] = e; sum += e; }
#pragma unroll
        for (int off = 16; off; off >>= 1) sum += __shfl_xor_sync(0xffffffffu, sum, off);
        float inv = 1.0f / sum;
        for (int s = lane; s < S_; s += 32) s_alpha[s] *= inv;
    }
    __syncthreads();

    // atten: e = tid (512 dims)
    {
        const float* r = rnn + (long)b * S_ * E_ + tid;
        float acc = 0.0f;
#pragma unroll 4
        for (int s = 0; s < S_; s++) acc += s_alpha[s] * r[(long)s * E_];
        d_x[b * KTOT + tid] = acc;
    }
    // g_t embedding
    if (tid < D_) {
        int tok = gtruths[b * T_ + t];
        d_x[b * KTOT + 768 + tid] = emb[(long)tok * D_ + tid];
    }
}

// ---------------------------------------------------------------------------
// LSTM gate GEMM: gates[2048][32] = W[2048][1536] x X[1536][32]
// grid 128 blocks (16 gate rows each), 128 threads.
// Warp w owns rows w*4..w*4+3; lane = batch. Register-double-buffered staging.
// ---------------------------------------------------------------------------
#define LMT 16
#define LKC 128
__global__ __launch_bounds__(128) void lstm_kernel(const float* __restrict__ W_ih,
                                                   const float* __restrict__ b_ih,
                                                   const float* __restrict__ W_hh,
                                                   const float* __restrict__ b_hh) {
    __shared__ __align__(16) float Ws[LMT][LKC];
    __shared__ __align__(16) float Xs[B_][LKC + 4];
    int g0 = blockIdx.x * LMT;
    int tid = threadIdx.x, lane = tid & 31, w = tid >> 5;

    float acc0 = 0.f, acc1 = 0.f, acc2 = 0.f, acc3 = 0.f;
    float4 wreg[4], xreg[8];

    // prefetch chunk 0
    {
        int k0 = 0;
#pragma unroll
        for (int it = 0; it < 4; it++) {
            int i = tid + it * 128;
            int r = i >> 5, c4 = (i & 31) * 4;
            wreg[it] = *(const float4*)(W_ih + (long)(g0 + r) * 1024 + k0 + c4);
        }
#pragma unroll
        for (int it = 0; it < 8; it++) {
            int i = tid + it * 128;
            int bb = i >> 5, c4 = (i & 31) * 4;
            xreg[it] = *(const float4*)(d_x + bb * KTOT + k0 + c4);
        }
    }

    for (int k0 = 0; k0 < KTOT; k0 += LKC) {
        // commit regs to smem
#pragma unroll
        for (int it = 0; it < 4; it++) {
            int i = tid + it * 128;
            int r = i >> 5, c4 = (i & 31) * 4;
            *(float4*)&Ws[r][c4] = wreg[it];
        }
#pragma unroll
        for (int it = 0; it < 8; it++) {
            int i = tid + it * 128;
            int bb = i >> 5, c4 = (i & 31) * 4;
            *(float4*)&Xs[bb][c4] = xreg[it];
        }
        __syncthreads();

        // prefetch next chunk
        int kn = k0 + LKC;
        if (kn < KTOT) {
#pragma unroll
            for (int it = 0; it < 4; it++) {
                int i = tid + it * 128;
                int r = i >> 5, c4 = (i & 31) * 4;
                const float* src = (kn < 1024)
                    ? W_ih + (long)(g0 + r) * 1024 + kn + c4
                    : W_hh + (long)(g0 + r) * 512 + (kn - 1024) + c4;
                wreg[it] = *(const float4*)src;
            }
#pragma unroll
            for (int it = 0; it < 8; it++) {
                int i = tid + it * 128;
                int bb = i >> 5, c4 = (i & 31) * 4;
                xreg[it] = *(const float4*)(d_x + bb * KTOT + kn + c4);
            }
        }

        // compute
#pragma unroll 8
        for (int kk = 0; kk < LKC; kk += 4) {
            float4 x  = *(const float4*)&Xs[lane][kk];
            float4 w0 = *(const float4*)&Ws[w * 4 + 0][kk];
            float4 w1 = *(const float4*)&Ws[w * 4 + 1][kk];
            float4 w2 = *(const float4*)&Ws[w * 4 + 2][kk];
            float4 w3 = *(const float4*)&Ws[w * 4 + 3][kk];
            acc0 += w0.x * x.x + w0.y * x.y + w0.z * x.z + w0.w * x.w;
            acc1 += w1.x * x.x + w1.y * x.y + w1.z * x.z + w1.w * x.w;
            acc2 += w2.x * x.x + w2.y * x.y + w2.z * x.z + w2.w * x.w;
            acc3 += w3.x * x.x + w3.y * x.y + w3.z * x.z + w3.w * x.w;
        }
        __syncthreads();
    }

    int g = g0 + w * 4;
    d_gatesT[(g + 0) * B_ + lane] = acc0 + b_ih[g + 0] + b_hh[g + 0];
    d_gatesT[(g + 1) * B_ + lane] = acc1 + b_ih[g + 1] + b_hh[g + 1];
    d_gatesT[(g + 2) * B_ + lane] = acc2 + b_ih[g + 2] + b_hh[g + 2];
    d_gatesT[(g + 3) * B_ + lane] = acc3 + b_ih[g + 3] + b_hh[g + 3];
}

// Final pointwise: gates of step T_-1 -> Hall[T_-1]   (grid B_, 512 thr)
__global__ void final_pw_kernel() {
    int b = blockIdx.x;
    int j = threadIdx.x;
    float gi = d_gatesT[j * B_ + b];
    float gf = d_gatesT[(H_ + j) * B_ + b];
    float gg = d_gatesT[(2 * H_ + j) * B_ + b];
    float go = d_gatesT[(3 * H_ + j) * B_ + b];
    float c = sigf(gf) * d_cx[b * H_ + j] + sigf(gi) * tanhf(gg);
    float h = sigf(go) * tanhf(c);
    d_Hall[((long)(T_ - 1) * B_ + b) * H_ + j] = h;
}

// ---------------------------------------------------------------------------
// Logits GEMM: out[m, v] = Hall[m,:]·W_fc[v,:] + b_fc[v]
// M=1280 (t*B_+b), N=50000, K=512. 128x128x8 tiles, 8x8/thread, reg prefetch.
// ---------------------------------------------------------------------------
#define GBM 128
#define GBN 128
#define GBK 8
__global__ __launch_bounds__(256, 2)
void gemm_kernel(const float* __restrict__ Wfc,
                 const float* __restrict__ bfc,
                 float* __restrict__ out) {
    __shared__ float As[GBK][GBM];
    __shared__ float Bs[GBK][GBN];
    int m0 = blockIdx.y * GBM;
    int n0 = blockIdx.x * GBN;
    int tid = threadIdx.x;
    int ar = tid >> 1;          // 0..127
    int ac = (tid & 1) * 4;     // 0 or 4
    int tx = tid & 15, ty = tid >> 4;

    float acc[8][8];
#pragma unroll
    for (int i = 0; i < 8; i++)
#pragma unroll
        for (int j = 0; j < 8; j++) acc[i][j] = 0.0f;

    int nrow = n0 + ar;
    const float* Arow = d_Hall + (long)(m0 + ar) * H_ + ac;
    const float* Brow = (nrow < V_) ? (Wfc + (long)nrow * H_ + ac) : nullptr;

    float4 av = *(const float4*)(Arow);
    float4 bv = Brow ? *(const float4*)(Brow) : make_float4(0.f, 0.f, 0.f, 0.f);

    for (int k0 = 0; k0 < H_; k0 += GBK) {
        As[ac + 0][ar] = av.x; As[ac + 1][ar] = av.y;
        As[ac + 2][ar] = av.z; As[ac + 3][ar] = av.w;
        Bs[ac + 0][ar] = bv.x; Bs[ac + 1][ar] = bv.y;
        Bs[ac + 2][ar] = bv.z; Bs[ac + 3][ar] = bv.w;
        __syncthreads();

        int kn = k0 + GBK;
        if (kn < H_) {
            av = *(const float4*)(Arow + kn);
            bv = Brow ? *(const float4*)(Brow + kn) : make_float4(0.f, 0.f, 0.f, 0.f);
        }

#pragma unroll
        for (int k = 0; k < GBK; k++) {
            float a[8], b[8];
#pragma unroll
            for (int i = 0; i < 8; i++) a[i] = As[k][ty * 8 + i];
#pragma unroll
            for (int j = 0; j < 8; j++) b[j] = Bs[k][tx * 8 + j];
#pragma unroll
            for (int i = 0; i < 8; i++)
#pragma unroll
                for (int j = 0; j < 8; j++) acc[i][j] += a[i] * b[j];
        }
        __syncthreads();
    }

#pragma unroll
    for (int i = 0; i < 8; i++) {
        int m = m0 + ty * 8 + i;
#pragma unroll
        for (int j = 0; j < 8; j++) {
            int n = n0 + tx * 8 + j;
            if (n < V_) out[(long)m * V_ + n] = acc[i][j] + bfc[n];
        }
    }
}

// ---------------------------------------------------------------------------
// Argmax per logits row; preds.T layout [B_, T_] written as float
// ---------------------------------------------------------------------------
__global__ void argmax_kernel(const float* __restrict__ logits,
                              float* __restrict__ outp) {
    int m = blockIdx.x;  // t*B_+b
    int tid = threadIdx.x;
    __shared__ float sv[256];
    __shared__ int   si[256];
    const float* row = logits + (long)m * V_;
    float best = -INFINITY; int bi = 0;
    for (int v = tid; v < V_; v += 256) {
        float x = row[v];
        if (x > best) { best = x; bi = v; }
    }
    sv[tid] = best; si[tid] = bi;
    __syncthreads();
    for (int s = 128; s; s >>= 1) {
        if (tid < s) {
            if (sv[tid + s] > sv[tid] ||
                (sv[tid + s] == sv[tid] && si[tid + s] < si[tid])) {
                sv[tid] = sv[tid + s]; si[tid] = si[tid + s];
            }
        }
        __syncthreads();
    }
    if (tid == 0) {
        int t = m / B_, b = m % B_;
        outp[b * T_ + t] = (float)si[0];
    }
}

// ---------------------------------------------------------------------------
extern "C" void kernel_launch(void* const* d_in, const int* in_sizes, int n_in,
                              void* d_out, int out_size) {
    const float* rnn   = (const float*)d_in[0];
    const float* cnn   = (const float*)d_in[1];
    const int*   gtr   = (const int*)  d_in[2];
    const float* emb   = (const float*)d_in[3];
    const float* W_ih  = (const float*)d_in[4];
    const float* b_ih  = (const float*)d_in[5];
    const float* W_hh  = (const float*)d_in[6];
    const float* b_hh  = (const float*)d_in[7];
    const float* W_ws  = (const float*)d_in[8];
    const float* b_ws  = (const float*)d_in[9];
    const float* W_uh  = (const float*)d_in[10];
    const float* b_uh  = (const float*)d_in[11];
    const float* W_v   = (const float*)d_in[12];
    const float* b_v   = (const float*)d_in[13];
    const float* W_fc  = (const float*)d_in[14];
    const float* b_fc  = (const float*)d_in[15];
    float* out = (float*)d_out;

    uh_kernel<<<dim3(A_ / 64, (B_ * S_) / 64), 256>>>(rnn, W_uh, b_uh);
    for (int t = 0; t < T_; t++) {
        attn_kernel<<<B_, 512>>>(t, rnn, cnn, emb, gtr, W_ws, b_ws, W_v, b_v);
        lstm_kernel<<<G4 / LMT, 128>>>(W_ih, b_ih, W_hh, b_hh);
    }
    final_pw_kernel<<<B_, 512>>>();

    dim3 ggrid((V_ + GBN - 1) / GBN, (T_ * B_) / GBM);
    gemm_kernel<<<ggrid, 256>>>(W_fc, b_fc, out);

    long logits_elems = (long)T_ * B_ * V_;
    if ((long)out_size >= logits_elems + (long)B_ * T_) {
        argmax_kernel<<<T_ * B_, 256>>>(out, out + logits_elems);
    }
}